// round 6
// baseline (speedup 1.0000x reference)
#include <cuda_runtime.h>
#include <stdint.h>

#define N 96
#define D 64
#define C 21
#define MARGIN_F 0.3f
#define ONE_F_BITS 0x3F800000u

// Scratch (no allocations allowed in kernel_launch)
__device__ float          g_mat[N * N];           // -(cosine sim)  [i, j]
__device__ unsigned char  g_sames[N * N];         // share-a-label & i!=j
__device__ unsigned char  g_diffs[N * N];         // !share-a-label (diag NOT filled)
// B[i,p,n] = diffs[i,n] & viol[i,p,n], float-encoded (0x0 / 0x3F800000),
// 96 floats per (i,p) = 24 uint4.  Total 96*96*24*16 B = 3.4 MB (L2-resident).
__device__ uint4          g_B4[N * N * 24];

// ---------------------------------------------------------------------------
// Kernel 1: mat[i,j], sames, diffs.  Grid: 96 blocks (i), 96 threads (j).
// ---------------------------------------------------------------------------
__global__ void precompute_kernel(const float* __restrict__ logits,
                                  const float* __restrict__ labels,
                                  const float* __restrict__ feat2) {
    const int i = blockIdx.x;
    const int j = threadIdx.x;

    __shared__ float xs[D];
    __shared__ float li[C];
    __shared__ float inv_nx;

    if (j < D) xs[j] = logits[i * D + j];
    if (j < C) li[j] = labels[i * C + j];
    __syncthreads();

    if (j == 0) {
        float s = 0.f;
        #pragma unroll
        for (int c = 0; c < D; c++) s += xs[c] * xs[c];
        inv_nx = 1.0f / fmaxf(sqrtf(s), 1e-12f);
    }
    __syncthreads();

    // thread j: dot(x_i, y_j), ||y_j||
    float dot = 0.f, nyy = 0.f;
    #pragma unroll
    for (int c = 0; c < D; c++) {
        float y = feat2[j * D + c];
        dot += xs[c] * y;
        nyy += y * y;
    }
    const float inv_ny = 1.0f / fmaxf(sqrtf(nyy), 1e-12f);
    g_mat[i * N + j] = -(dot * inv_nx * inv_ny);

    // label structure
    float ld = 0.f;
    #pragma unroll
    for (int c = 0; c < C; c++) ld += li[c] * labels[j * C + c];
    const bool share = (ld > 0.0f);
    g_sames[i * N + j] = (share && (i != j)) ? 1 : 0;
    g_diffs[i * N + j] = share ? 0 : 1;           // diagonal NOT filled (matches ref)
}

// ---------------------------------------------------------------------------
// Kernel 2: B[i,p,n] = diffs[i,n] && (mat[i,n] - mat[i,p] <= MARGIN)
// stored as float bit patterns (0x0 / 0x3F800000), 24 uint4 per (i,p).
// Grid: 96 blocks (i), 96 threads (p).
// ---------------------------------------------------------------------------
__global__ void build_B_kernel() {
    const int i = blockIdx.x;
    const int p = threadIdx.x;

    __shared__ float         mrow[N];
    __shared__ unsigned char drow[N];
    mrow[p] = g_mat[i * N + p];
    drow[p] = g_diffs[i * N + p];
    __syncthreads();

    const float mp = mrow[p];

    uint32_t w[N];
    #pragma unroll
    for (int nn = 0; nn < N; nn++) {
        w[nn] = (drow[nn] && (mrow[nn] - mp <= MARGIN_F)) ? ONE_F_BITS : 0u;
    }

    uint4* dst = &g_B4[(i * N + p) * 24];
    #pragma unroll
    for (int v = 0; v < 24; v++)
        dst[v] = make_uint4(w[4 * v + 0], w[4 * v + 1], w[4 * v + 2], w[4 * v + 3]);
}

// ---------------------------------------------------------------------------
// Kernel 3: fill output (float32 0.0/1.0). One thread per uint4 (4 floats).
// out[i,j,k,n] = valid-triple ? (B[i,j,n] | B[i,k,n]) : 0   (bitwise OR on
// float-encoded bools is exact).
// total uint4 = 96*96*96*24 = 21,233,664 -> 82944 blocks x 256 threads exactly.
// ---------------------------------------------------------------------------
__global__ void fill_kernel(uint4* __restrict__ out) {
    const int idx = blockIdx.x * blockDim.x + threadIdx.x;

    const int v  = idx % 24;
    const int t  = idx / 24;
    const int k  = t % N;
    const int t2 = t / N;
    const int j  = t2 % N;
    const int i  = t2 / N;

    uint4 r = make_uint4(0u, 0u, 0u, 0u);
    if ((j < k) && g_sames[i * N + j] && g_sames[i * N + k]) {
        const uint4 a = g_B4[(i * N + j) * 24 + v];
        const uint4 b = g_B4[(i * N + k) * 24 + v];
        r = make_uint4(a.x | b.x, a.y | b.y, a.z | b.z, a.w | b.w);
    }
    out[idx] = r;
}

// ---------------------------------------------------------------------------
extern "C" void kernel_launch(void* const* d_in, const int* in_sizes, int n_in,
                              void* d_out, int out_size) {
    const float* logits = (const float*)d_in[0];   // [96, 64]
    const float* labels = (const float*)d_in[1];   // [96, 21]
    const float* feat2  = (const float*)d_in[2];   // [96, 64]

    precompute_kernel<<<N, N>>>(logits, labels, feat2);
    build_B_kernel<<<N, N>>>();

    // 96^4 floats / 4-per-uint4 = 21,233,664 uint4 = 82944 * 256
    fill_kernel<<<82944, 256>>>((uint4*)d_out);
}

// round 7
// speedup vs baseline: 1.2497x; 1.2497x over previous
#include <cuda_runtime.h>
#include <stdint.h>

#define N 96
#define D 64
#define C 21
#define MARGIN_F 0.3f
#define ONE_F_BITS 0x3F800000u

// Scratch (no allocations allowed in kernel_launch)
__device__ unsigned char  g_sames[N * N];         // share-a-label & i!=j
// B[i,p,n] = diffs[i,n] & viol[i,p,n], float-encoded (0x0 / 0x3F800000),
// 96 floats per (i,p) = 24 uint4.  Total 3.4 MB (L2-resident).
__device__ uint4          g_B4[N * N * 24];

// ---------------------------------------------------------------------------
// Kernel A (fused): block i computes mat row i, sames/diffs row i, then the
// whole B[i, :, :] slab.  Grid: 96 blocks (i), 96 threads.
// ---------------------------------------------------------------------------
__global__ void prep_kernel(const float* __restrict__ logits,
                            const float* __restrict__ labels,
                            const float* __restrict__ feat2) {
    const int i = blockIdx.x;
    const int j = threadIdx.x;           // 0..95

    __shared__ float         xs[D];
    __shared__ float         li[C];
    __shared__ float         inv_nx;
    __shared__ float         mrow[N];    // mat[i, :]
    __shared__ unsigned char drow[N];    // diffs[i, :]  (diag NOT filled)

    if (j < D) xs[j] = logits[i * D + j];
    if (j < C) li[j] = labels[i * C + j];
    __syncthreads();

    if (j == 0) {
        float s = 0.f;
        #pragma unroll
        for (int c = 0; c < D; c++) s += xs[c] * xs[c];
        inv_nx = 1.0f / fmaxf(sqrtf(s), 1e-12f);
    }
    __syncthreads();

    // thread j: dot(x_i, y_j), ||y_j||
    float dot = 0.f, nyy = 0.f;
    #pragma unroll
    for (int c = 0; c < D; c++) {
        float y = feat2[j * D + c];
        dot += xs[c] * y;
        nyy += y * y;
    }
    const float inv_ny = 1.0f / fmaxf(sqrtf(nyy), 1e-12f);
    mrow[j] = -(dot * inv_nx * inv_ny);

    // label structure
    float ld = 0.f;
    #pragma unroll
    for (int c = 0; c < C; c++) ld += li[c] * labels[j * C + c];
    const bool share = (ld > 0.0f);
    g_sames[i * N + j] = (share && (i != j)) ? 1 : 0;
    drow[j] = share ? 0 : 1;             // diagonal kept True when row all-zero (matches ref)
    __syncthreads();

    // Phase 2: B[i, p, n] = diffs[i,n] && (mat[i,n] - mat[i,p] <= MARGIN)
    const int   p  = j;
    const float mp = mrow[p];

    uint32_t w[N];
    #pragma unroll
    for (int nn = 0; nn < N; nn++)
        w[nn] = (drow[nn] && (mrow[nn] - mp <= MARGIN_F)) ? ONE_F_BITS : 0u;

    uint4* dst = &g_B4[(i * N + p) * 24];
    #pragma unroll
    for (int v = 0; v < 24; v++)
        dst[v] = make_uint4(w[4 * v + 0], w[4 * v + 1], w[4 * v + 2], w[4 * v + 3]);
}

// ---------------------------------------------------------------------------
// Kernel B: tiled fill.  Block = (jt, kt, i) covering an 8x8 (j,k) tile.
//   jt > kt  : entire tile j>=k -> pure zero fill, no reads.
//   jt <= kt : load 16 B-rows (6 KB) to smem, emit 8*8*24 uint4 (24 KB).
// out[i,j,k,n] = (sames[i,j] && sames[i,k] && j<k) ? (B[i,j,n] | B[i,k,n]) : 0
// ---------------------------------------------------------------------------
#define TJ 8
#define TK 8

__global__ void fill_kernel(uint4* __restrict__ out) {
    const int jt = blockIdx.x;
    const int kt = blockIdx.y;
    const int i  = blockIdx.z;
    const int tid = threadIdx.x;         // 0..255

    const int j0 = jt * TJ;
    const int k0 = kt * TK;

    // uint4 index of out[i][j0][k0][0]
    uint4* __restrict__ obase = out + ((size_t)(i * N + j0) * N + k0) * 24;

    if (jt > kt) {
        // j >= k everywhere -> all zeros, no reads
        const uint4 z = make_uint4(0u, 0u, 0u, 0u);
        #pragma unroll
        for (int it = 0; it < 6; it++) {
            const int l  = it * 256 + tid;       // 0..1535
            const int jj = l / (TK * 24);
            const int r  = l - jj * (TK * 24);   // kk*24 + v
            obase[(size_t)jj * (N * 24) + r] = z;
        }
        return;
    }

    __shared__ uint4         sBj[TJ][24];
    __shared__ uint4         sBk[TK][24];
    __shared__ unsigned char ssj[TJ];
    __shared__ unsigned char ssk[TK];

    // load 384 uint4 (rows 0-7 -> sBj, 8-15 -> sBk)
    {
        int l = tid;                       // first 256
        {
            const int row = l / 24, v = l % 24;
            const int src_p = (row < TJ) ? (j0 + row) : (k0 + row - TJ);
            uint4 val = g_B4[(i * N + src_p) * 24 + v];
            if (row < TJ) sBj[row][v] = val; else sBk[row - TJ][v] = val;
        }
        l = tid + 256;                     // remaining 128
        if (l < 384) {
            const int row = l / 24, v = l % 24;
            const int src_p = (row < TJ) ? (j0 + row) : (k0 + row - TJ);
            uint4 val = g_B4[(i * N + src_p) * 24 + v];
            if (row < TJ) sBj[row][v] = val; else sBk[row - TJ][v] = val;
        }
        if (tid < TJ)                 ssj[tid] = g_sames[i * N + j0 + tid];
        else if (tid < TJ + TK)       ssk[tid - TJ] = g_sames[i * N + k0 + (tid - TJ)];
    }
    __syncthreads();

    const bool diag = (jt == kt);
    const uint4 z = make_uint4(0u, 0u, 0u, 0u);

    #pragma unroll
    for (int it = 0; it < 6; it++) {
        const int l  = it * 256 + tid;           // 0..1535
        const int jj = l / (TK * 24);
        const int r  = l - jj * (TK * 24);
        const int kk = r / 24;
        const int v  = r - kk * 24;

        const bool valid = ssj[jj] && ssk[kk] && (!diag || jj < kk);
        uint4 res = z;
        if (valid) {
            const uint4 a = sBj[jj][v];
            const uint4 b = sBk[kk][v];
            res = make_uint4(a.x | b.x, a.y | b.y, a.z | b.z, a.w | b.w);
        }
        obase[(size_t)jj * (N * 24) + r] = res;
    }
}

// ---------------------------------------------------------------------------
extern "C" void kernel_launch(void* const* d_in, const int* in_sizes, int n_in,
                              void* d_out, int out_size) {
    const float* logits = (const float*)d_in[0];   // [96, 64]
    const float* labels = (const float*)d_in[1];   // [96, 21]
    const float* feat2  = (const float*)d_in[2];   // [96, 64]

    prep_kernel<<<N, N>>>(logits, labels, feat2);

    fill_kernel<<<dim3(N / TJ, N / TK, N), 256>>>((uint4*)d_out);
}